// round 15
// baseline (speedup 1.0000x reference)
#include <cuda_runtime.h>
#include <cuda_bf16.h>
#include <math.h>
#include <stdint.h>

// Problem constants
#define NB    2048
#define NC    100000
#define NPAD  100096      // 782 * 128
#define ND    128
#define KNN   200
#define NCL   1000
#define GCONST 0.005f

#define HB    144
#define HBW   0.5f
#define HRANGE 72.0f      // rank-200 rel <= ~60 for all queries (>10 sigma margin)
#define CAPQ  8192        // prefilter capacity/query (mean ~2250, max ~3800)
#define SMAX  4096        // smem staging capacity in k_sel
#define FCAP  512         // finalist capacity/query (expected ~235)
#define TMARG 1.0f        // margin >> bf16 dot noise (4 sigma ~ 0.22) + bin width

// -------- device scratch --------
static __device__ __align__(16) __nv_bfloat16 g_chi[(size_t)NPAD * ND];
static __device__ __align__(16) __nv_bfloat16 g_fhi[(size_t)NB * ND];
static __device__ float  g_cn[NPAD];
static __device__ float  g_fq[NB];
static __device__ int    g_cnt[NB];
static __device__ __align__(16) float2 g_cand[(size_t)NB * CAPQ];  // (rel, idx)
static __device__ float2 g_fin[(size_t)NB * FCAP];                 // (d2, idx)
static __device__ int    g_fcnt[NB];
static __device__ int    g_lab64;

// -------- baseline-PTX tensor helpers --------
__device__ __forceinline__ uint32_t sm2u(const void* p) {
    uint32_t a;
    asm("{ .reg .u64 t; cvta.to.shared.u64 t, %1; cvt.u32.u64 %0, t; }" : "=r"(a) : "l"(p));
    return a;
}
__device__ __forceinline__ void ldsm4(uint32_t& r0, uint32_t& r1, uint32_t& r2, uint32_t& r3,
                                      uint32_t addr) {
    asm volatile("ldmatrix.sync.aligned.m8n8.x4.shared.b16 {%0,%1,%2,%3}, [%4];"
                 : "=r"(r0), "=r"(r1), "=r"(r2), "=r"(r3) : "r"(addr));
}
__device__ __forceinline__ void mma16816(float* c, const uint32_t* a, const uint32_t* b) {
    asm volatile(
        "mma.sync.aligned.m16n8k16.row.col.f32.bf16.bf16.f32 "
        "{%0,%1,%2,%3},{%4,%5,%6,%7},{%8,%9},{%0,%1,%2,%3};"
        : "+f"(c[0]), "+f"(c[1]), "+f"(c[2]), "+f"(c[3])
        : "r"(a[0]), "r"(a[1]), "r"(a[2]), "r"(a[3]), "r"(b[0]), "r"(b[1]));
}

// SMEM layout: 2 tiles of 128 rows x 136 bf16 (stride 272B, LDSM conflict-free)
#define TSTR   136
#define TBYTES (128 * TSTR * 2)   // 34816
#define TA     0
#define TB     TBYTES
#define OFF_CN (2 * TBYTES)       // float cn[128]
#define OFF_SC (OFF_CN + 512)     // int scnt[128]
#define OFF_GB (OFF_SC + 512)     // int sgb[128]
#define SMEM_SZ (OFF_GB + 512)    // ~71 KB -> 2 CTAs/SM

// ---------------- K0: zero counters + label dtype sniff ----------------
__global__ void k_zero(const int* __restrict__ labw) {
    int i = blockIdx.x * blockDim.x + threadIdx.x;
    if (i < NB) g_cnt[i] = 0;
    if (i == 0) {
        int any = 0;
        #pragma unroll
        for (int j = 1; j < 64; j += 2) any |= labw[j];
        g_lab64 = (any == 0) ? 1 : 0;
    }
}

// ---------------- K1: norms (bit-exact XLA pattern) + bf16 cast ----------
__global__ void k_prep(const float* __restrict__ feats, const float* __restrict__ cents) {
    int warp = (blockIdx.x * blockDim.x + threadIdx.x) >> 5;
    int lane = threadIdx.x & 31;
    if (warp >= NPAD + NB) return;
    bool isC = (warp < NPAD);
    int row = isC ? warp : warp - NPAD;
    if (isC && row >= NC) {   // pad rows
        #pragma unroll
        for (int t = 0; t < 4; t++)
            g_chi[(size_t)row * ND + lane + 32 * t] = __float2bfloat16(0.f);
        if (lane == 0) g_cn[row] = 1e9f;
        return;
    }
    const float* src = isC ? (cents + (size_t)row * ND) : (feats + (size_t)row * ND);
    float x[4];
    #pragma unroll
    for (int t = 0; t < 4; t++) x[t] = src[lane + 32 * t];

    float s = __fmul_rn(x[0], x[0]);
    s = __fadd_rn(s, __fmul_rn(x[1], x[1]));
    s = __fadd_rn(s, __fmul_rn(x[2], x[2]));
    s = __fadd_rn(s, __fmul_rn(x[3], x[3]));
    #pragma unroll
    for (int o = 16; o; o >>= 1)
        s = __fadd_rn(s, __shfl_down_sync(0xffffffffu, s, o));
    if (lane == 0) { if (isC) g_cn[row] = s; else g_fq[row] = s; }

    #pragma unroll
    for (int t = 0; t < 4; t++) {
        __nv_bfloat16 hi = __float2bfloat16(x[t]);
        size_t o = (size_t)row * ND + lane + 32 * t;
        if (isC) g_chi[o] = hi; else g_fhi[o] = hi;
    }
}

// ---------------- K2: bf16 mma.sync GEMM + aggregated prefilter ----------
__global__ void __launch_bounds__(256, 2) k_gemm() {
    extern __shared__ char smem[];
    uint32_t sb = sm2u(smem);
    int tid = threadIdx.x;
    int wid = tid >> 5, lid = tid & 31;
    int m0 = blockIdx.x * 128;
    int n0 = blockIdx.y * 128;

    if (tid < 128) {
        *(float*)(smem + OFF_CN + tid * 4) = g_cn[n0 + tid];
        *(int*)(smem + OFF_SC + tid * 4) = 0;
    }

    // fill 2 tiles: row-major 128 x 128 bf16, padded stride 136 elems
    for (int t = tid; t < 2048; t += 256) {
        int r = t >> 4, k8 = (t & 15) * 8;
        uint32_t so = (uint32_t)(r * TSTR + k8) * 2;
        *(uint4*)(smem + TA + so) = *(const uint4*)(g_fhi + (size_t)(m0 + r) * ND + k8);
        *(uint4*)(smem + TB + so) = *(const uint4*)(g_chi + (size_t)(n0 + r) * ND + k8);
    }
    __syncthreads();

    int wm = wid & 1, wn = wid >> 1;
    int lrow = lid & 15;
    int cg   = lid >> 4;

    float c[4][4][4];
    #pragma unroll
    for (int i = 0; i < 4; i++)
        #pragma unroll
        for (int j = 0; j < 4; j++)
            #pragma unroll
            for (int v = 0; v < 4; v++) c[i][j][v] = 0.f;

    #pragma unroll
    for (int kk = 0; kk < 128; kk += 16) {
        uint32_t af[4][4], bf[2][4];
        #pragma unroll
        for (int ms = 0; ms < 4; ms++) {
            uint32_t ad = sb + TA + (uint32_t)((wm * 64 + ms * 16 + lrow) * TSTR + kk + cg * 8) * 2;
            ldsm4(af[ms][0], af[ms][1], af[ms][2], af[ms][3], ad);
        }
        #pragma unroll
        for (int g = 0; g < 2; g++) {
            uint32_t bd = sb + TB + (uint32_t)((wn * 32 + g * 16 + lrow) * TSTR + kk + cg * 8) * 2;
            ldsm4(bf[g][0], bf[g][1], bf[g][2], bf[g][3], bd);
        }
        #pragma unroll
        for (int ms = 0; ms < 4; ms++)
            #pragma unroll
            for (int ns = 0; ns < 4; ns++) {
                uint32_t b2[2] = { bf[ns >> 1][ns & 1], bf[ns >> 1][(ns & 1) + 2] };
                mma16816(c[ms][ns], af[ms], b2);
            }
    }

    // ---- epilogue: CTA-aggregated candidate append ----
    const float* cns = (const float*)(smem + OFF_CN);
    int* scnt = (int*)(smem + OFF_SC);
    int* sgb  = (int*)(smem + OFF_GB);
    uint32_t masks[8];
    int lbase[8];

    #pragma unroll
    for (int p = 0; p < 8; p++) {
        int ms = p >> 1, half = p & 1;
        int qloc = wm * 64 + ms * 16 + half * 8 + (lid >> 2);
        uint32_t mk = 0; int cnt = 0;
        #pragma unroll
        for (int ns = 0; ns < 4; ns++)
            #pragma unroll
            for (int e = 0; e < 2; e++) {
                int nn = wn * 32 + 2 * (lid & 3) + ns * 8 + e;
                float rel = cns[nn] - 2.0f * c[ms][ns][half * 2 + e];
                if (rel < HRANGE) { mk |= 1u << (ns * 2 + e); cnt++; }
            }
        masks[p] = mk;
        lbase[p] = cnt ? atomicAdd(&scnt[qloc], cnt) : 0;
    }
    __syncthreads();
    if (tid < 128) {
        int c128 = scnt[tid];
        sgb[tid] = c128 ? atomicAdd(&g_cnt[m0 + tid], c128) : 0;
    }
    __syncthreads();

    #pragma unroll
    for (int p = 0; p < 8; p++) {
        uint32_t mk = masks[p];
        if (!mk) continue;
        int ms = p >> 1, half = p & 1;
        int qloc = wm * 64 + ms * 16 + half * 8 + (lid >> 2);
        int q = m0 + qloc;
        int base = sgb[qloc] + lbase[p];
        int r = 0;
        #pragma unroll
        for (int ns = 0; ns < 4; ns++)
            #pragma unroll
            for (int e = 0; e < 2; e++) {
                if (mk & (1u << (ns * 2 + e))) {
                    int nn = wn * 32 + 2 * (lid & 3) + ns * 8 + e;
                    float rel = cns[nn] - 2.0f * c[ms][ns][half * 2 + e];
                    int pos = base + r; r++;
                    if (pos < CAPQ)
                        g_cand[(size_t)q * CAPQ + pos] = make_float2(rel, __int_as_float(n0 + nn));
                }
            }
    }
}

// ---------------- K3: select finalists (single global pass) ---------------
__global__ void __launch_bounds__(256, 4) k_sel(const float* __restrict__ feats,
                                                const float* __restrict__ cents) {
    __shared__ float srel[SMAX];     // staged rel values (16 KB)
    __shared__ int   hist[HB];
    __shared__ float thr_s;
    __shared__ int   fcnt;
    __shared__ float ff[ND];

    int q = blockIdx.x, tid = threadIdx.x;
    int M = g_cnt[q]; if (M > CAPQ) M = CAPQ;
    const float2* cand = g_cand + (size_t)q * CAPQ;
    const float4* cand4 = (const float4*)cand;
    int Mp = (M + 1) >> 1;

    for (int i = tid; i < HB; i += 256) hist[i] = 0;
    if (tid == 0) fcnt = 0;
    if (tid < ND) ff[tid] = feats[(size_t)q * ND + tid];
    __syncthreads();

    // single streaming pass: hist + stage rel into smem
    #pragma unroll 2
    for (int i = tid; i < Mp; i += 256) {
        float4 v = cand4[i];
        {
            int b = (int)(v.x * 2.0f);
            if (b < 0) b = 0;
            if (b > HB - 1) b = HB - 1;
            atomicAdd(&hist[b], 1);
            if (2 * i < SMAX) srel[2 * i] = v.x;
        }
        if (2 * i + 1 < M) {
            int b = (int)(v.z * 2.0f);
            if (b < 0) b = 0;
            if (b > HB - 1) b = HB - 1;
            atomicAdd(&hist[b], 1);
            if (2 * i + 1 < SMAX) srel[2 * i + 1] = v.z;
        }
    }
    __syncthreads();
    if (tid == 0) {
        int cum = 0; float t = HRANGE;
        for (int b = 0; b < HB; b++) {
            cum += hist[b];
            if (cum >= KNN) { t = (float)(b + 1) * HBW; break; }
        }
        thr_s = t;
    }
    __syncthreads();
    float t = thr_s + TMARG;
    float fq = g_fq[q];
    float2* fin = g_fin + (size_t)q * FCAP;
    int Ms = (M < SMAX) ? M : SMAX;

    // rescan from smem; accepted -> idx from L2-hot g_cand + exact recompute
    for (int i = tid; i < Ms; i += 256) {
        if (srel[i] < t) {
            int ix = __float_as_int(cand[i].y);
            const float4* cr = (const float4*)(cents + (size_t)ix * ND);
            float acc = 0.f;
            #pragma unroll
            for (int k0 = 0; k0 < 32; k0 += 4) {
                float4 b0 = cr[k0 + 0], b1 = cr[k0 + 1], b2 = cr[k0 + 2], b3 = cr[k0 + 3];
                int kb = k0 * 4;
                acc = fmaf(ff[kb + 0],  b0.x, acc); acc = fmaf(ff[kb + 1],  b0.y, acc);
                acc = fmaf(ff[kb + 2],  b0.z, acc); acc = fmaf(ff[kb + 3],  b0.w, acc);
                acc = fmaf(ff[kb + 4],  b1.x, acc); acc = fmaf(ff[kb + 5],  b1.y, acc);
                acc = fmaf(ff[kb + 6],  b1.z, acc); acc = fmaf(ff[kb + 7],  b1.w, acc);
                acc = fmaf(ff[kb + 8],  b2.x, acc); acc = fmaf(ff[kb + 9],  b2.y, acc);
                acc = fmaf(ff[kb + 10], b2.z, acc); acc = fmaf(ff[kb + 11], b2.w, acc);
                acc = fmaf(ff[kb + 12], b3.x, acc); acc = fmaf(ff[kb + 13], b3.y, acc);
                acc = fmaf(ff[kb + 14], b3.z, acc); acc = fmaf(ff[kb + 15], b3.w, acc);
            }
            float d2 = __fadd_rn(__fadd_rn(fq, g_cn[ix]), __fmul_rn(-2.0f, acc));
            int p = atomicAdd(&fcnt, 1);
            if (p < FCAP) fin[p] = make_float2(d2, cand[i].y);
        }
    }
    // overflow fallback (M > SMAX): never expected, kept for safety
    for (int i = SMAX + tid; i < M; i += 256) {
        float2 v = cand[i];
        if (v.x < t) {
            int ix = __float_as_int(v.y);
            const float4* cr = (const float4*)(cents + (size_t)ix * ND);
            float acc = 0.f;
            #pragma unroll
            for (int k0 = 0; k0 < 32; k0 += 4) {
                float4 b0 = cr[k0 + 0], b1 = cr[k0 + 1], b2 = cr[k0 + 2], b3 = cr[k0 + 3];
                int kb = k0 * 4;
                acc = fmaf(ff[kb + 0],  b0.x, acc); acc = fmaf(ff[kb + 1],  b0.y, acc);
                acc = fmaf(ff[kb + 2],  b0.z, acc); acc = fmaf(ff[kb + 3],  b0.w, acc);
                acc = fmaf(ff[kb + 4],  b1.x, acc); acc = fmaf(ff[kb + 5],  b1.y, acc);
                acc = fmaf(ff[kb + 6],  b1.z, acc); acc = fmaf(ff[kb + 7],  b1.w, acc);
                acc = fmaf(ff[kb + 8],  b2.x, acc); acc = fmaf(ff[kb + 9],  b2.y, acc);
                acc = fmaf(ff[kb + 10], b2.z, acc); acc = fmaf(ff[kb + 11], b2.w, acc);
                acc = fmaf(ff[kb + 12], b3.x, acc); acc = fmaf(ff[kb + 13], b3.y, acc);
                acc = fmaf(ff[kb + 14], b3.z, acc); acc = fmaf(ff[kb + 15], b3.w, acc);
            }
            float d2 = __fadd_rn(__fadd_rn(fq, g_cn[ix]), __fmul_rn(-2.0f, acc));
            int p = atomicAdd(&fcnt, 1);
            if (p < FCAP) fin[p] = make_float2(d2, v.y);
        }
    }
    __syncthreads();
    if (tid == 0) g_fcnt[q] = (fcnt < FCAP) ? fcnt : FCAP;
}

// ---------------- K4: sort + weight + scatter + normalize + output --------
__global__ void __launch_bounds__(256, 4) k_out(const float* __restrict__ wt,
                                                const void* __restrict__ lab,
                                                float* __restrict__ out,
                                                int out_size) {
    __shared__ float sd[FCAP];
    __shared__ int   si[FCAP];
    __shared__ int   skey[256];
    __shared__ float swv[256];
    __shared__ float pcl[NCL];
    __shared__ float red[256];

    int q = blockIdx.x, tid = threadIdx.x;
    int Fc = g_fcnt[q];
    int P = 256; while (P < Fc) P <<= 1;   // <= FCAP = 512
    const float2* fin = g_fin + (size_t)q * FCAP;

    for (int i = tid; i < P; i += 256) {
        if (i < Fc) { float2 v = fin[i]; sd[i] = v.x; si[i] = __float_as_int(v.y); }
        else        { sd[i] = 1e30f;     si[i] = 0x7fffffff; }
    }
    __syncthreads();

    // bitonic ascending sort on (d2, idx), lower index on ties — canonical
    for (int len = 2; len <= P; len <<= 1) {
        for (int s = len >> 1; s > 0; s >>= 1) {
            for (int i = tid; i < P; i += 256) {
                int j = i ^ s;
                if (j > i) {
                    bool up = ((i & len) == 0);
                    float di = sd[i], dj = sd[j];
                    int   ii = si[i], ij = si[j];
                    bool  gt = (di > dj) || (di == dj && ii > ij);
                    if (gt == up) { sd[i] = dj; sd[j] = di; si[i] = ij; si[j] = ii; }
                }
            }
            __syncthreads();
        }
    }

    int Ke = (Fc < KNN) ? Fc : KNN;
    int is64 = g_lab64;
    {
        int j = tid;
        if (j < Ke) {
            float d2 = sd[j]; if (d2 < 0.f) d2 = 0.f;
            int ix = si[j];
            int lb = is64 ? (int)((const long long*)lab)[ix] : ((const int*)lab)[ix];
            skey[j] = lb * 256 + j;
            swv[j]  = expf(__fmul_rn(-d2, GCONST)) * expf(wt[ix]);
        } else {
            skey[j] = 0x7fffffff;
            swv[j]  = 0.f;
        }
    }
    __syncthreads();

    // bitonic sort 256 by (label, rank) key — one element per thread
    for (int len = 2; len <= 256; len <<= 1) {
        for (int s = len >> 1; s > 0; s >>= 1) {
            int i = tid, j = i ^ s;
            if (j > i) {
                bool up = ((i & len) == 0);
                int   ki = skey[i], kj = skey[j];
                float wi = swv[i],  wj = swv[j];
                if ((ki > kj) == up) { skey[i] = kj; skey[j] = ki; swv[i] = wj; swv[j] = wi; }
            }
            __syncthreads();
        }
    }

    for (int c = tid; c < NCL; c += 256) pcl[c] = 0.f;
    __syncthreads();

    // segment-head sums (within-label order = ascending rank — matches ref)
    {
        int j = tid;
        int key = skey[j];
        if (key != 0x7fffffff) {
            int lb = key >> 8;
            bool head = (j == 0) || ((skey[j - 1] >> 8) != lb);
            if (head) {
                float s = 0.f;
                for (int k2 = j; k2 < 256; k2++) {
                    int k = skey[k2];
                    if (k == 0x7fffffff || (k >> 8) != lb) break;
                    s += swv[k2];
                }
                pcl[lb] = s;
            }
        }
    }
    __syncthreads();

    float partial = 0.f;
    for (int c = tid; c < NCL; c += 256) {
        float p = pcl[c];
        if (p == 0.f) { p = 1e-10f; pcl[c] = p; }
        partial += p;
    }
    red[tid] = partial;
    __syncthreads();
    #pragma unroll
    for (int o = 128; o; o >>= 1) {
        if (tid < o) red[tid] += red[tid + o];
        __syncthreads();
    }
    float S = red[0];

    for (int c = tid; c < NCL; c += 256) {
        float pn = pcl[c] / S;
        size_t o1 = (size_t)q * NCL + c;
        size_t o2 = (size_t)NB * NCL + o1;
        if (o1 < (size_t)out_size) out[o1] = logf(pn);
        if (o2 < (size_t)out_size) out[o2] = pn;
    }
}

// ---------------- launch ----------------
extern "C" void kernel_launch(void* const* d_in, const int* in_sizes, int n_in,
                              void* d_out, int out_size) {
    const float* feats = (const float*)d_in[0];
    const float* cents = (const float*)d_in[1];
    const float* wt    = (const float*)d_in[2];
    const void*  lab   = d_in[3];

    cudaFuncSetAttribute(k_gemm, cudaFuncAttributeMaxDynamicSharedMemorySize, SMEM_SZ);

    k_zero<<<(NB + 255) / 256, 256>>>((const int*)lab);
    k_prep<<<((NPAD + NB) * 32 + 255) / 256, 256>>>(feats, cents);
    k_gemm<<<dim3(NB / 128, NPAD / 128), 256, SMEM_SZ>>>();
    k_sel<<<NB, 256>>>(feats, cents);
    k_out<<<NB, 256>>>(wt, lab, (float*)d_out, out_size);
}

// round 16
// speedup vs baseline: 1.1250x; 1.1250x over previous
#include <cuda_runtime.h>
#include <cuda_bf16.h>
#include <math.h>
#include <stdint.h>

// Problem constants
#define NB    2048
#define NC    100000
#define NPAD  100096      // 782 * 128
#define ND    128
#define KNN   200
#define NCL   1000
#define GCONST 0.005f

#define HB    144
#define HBW   0.5f
#define HRANGE 72.0f      // rank-200 rel <= ~60 for all queries (>10 sigma margin)
#define CAPQ  8192        // prefilter capacity/query (mean ~2250, max ~3800)
#define FCAP  512         // finalist capacity/query (expected ~235)
#define TMARG 1.0f        // margin >> bf16 dot noise (4 sigma ~ 0.22) + bin width
#define BROWS 64          // staged recompute batch rows

// -------- device scratch --------
static __device__ __align__(16) __nv_bfloat16 g_chi[(size_t)NPAD * ND];
static __device__ __align__(16) __nv_bfloat16 g_fhi[(size_t)NB * ND];
static __device__ float  g_cn[NPAD];
static __device__ float  g_fq[NB];
static __device__ int    g_cnt[NB];
static __device__ __align__(16) float2 g_cand[(size_t)NB * CAPQ];  // (rel, idx)
static __device__ float2 g_fin[(size_t)NB * FCAP];                 // (d2, idx)
static __device__ int    g_fcnt[NB];
static __device__ int    g_lab64;

// -------- baseline-PTX tensor helpers --------
__device__ __forceinline__ uint32_t sm2u(const void* p) {
    uint32_t a;
    asm("{ .reg .u64 t; cvta.to.shared.u64 t, %1; cvt.u32.u64 %0, t; }" : "=r"(a) : "l"(p));
    return a;
}
__device__ __forceinline__ void ldsm4(uint32_t& r0, uint32_t& r1, uint32_t& r2, uint32_t& r3,
                                      uint32_t addr) {
    asm volatile("ldmatrix.sync.aligned.m8n8.x4.shared.b16 {%0,%1,%2,%3}, [%4];"
                 : "=r"(r0), "=r"(r1), "=r"(r2), "=r"(r3) : "r"(addr));
}
__device__ __forceinline__ void mma16816(float* c, const uint32_t* a, const uint32_t* b) {
    asm volatile(
        "mma.sync.aligned.m16n8k16.row.col.f32.bf16.bf16.f32 "
        "{%0,%1,%2,%3},{%4,%5,%6,%7},{%8,%9},{%0,%1,%2,%3};"
        : "+f"(c[0]), "+f"(c[1]), "+f"(c[2]), "+f"(c[3])
        : "r"(a[0]), "r"(a[1]), "r"(a[2]), "r"(a[3]), "r"(b[0]), "r"(b[1]));
}

// SMEM layout: 2 tiles of 128 rows x 136 bf16 (stride 272B, LDSM conflict-free)
#define TSTR   136
#define TBYTES (128 * TSTR * 2)   // 34816
#define TA     0
#define TB     TBYTES
#define OFF_CN (2 * TBYTES)       // float cn[128]
#define OFF_SC (OFF_CN + 512)     // int scnt[128]
#define OFF_GB (OFF_SC + 512)     // int sgb[128]
#define SMEM_SZ (OFF_GB + 512)    // ~71 KB -> 2 CTAs/SM

// ---------------- K0: zero counters + label dtype sniff ----------------
__global__ void k_zero(const int* __restrict__ labw) {
    int i = blockIdx.x * blockDim.x + threadIdx.x;
    if (i < NB) g_cnt[i] = 0;
    if (i == 0) {
        int any = 0;
        #pragma unroll
        for (int j = 1; j < 64; j += 2) any |= labw[j];
        g_lab64 = (any == 0) ? 1 : 0;
    }
}

// ---------------- K1: norms (bit-exact XLA pattern) + bf16 cast ----------
__global__ void k_prep(const float* __restrict__ feats, const float* __restrict__ cents) {
    int warp = (blockIdx.x * blockDim.x + threadIdx.x) >> 5;
    int lane = threadIdx.x & 31;
    if (warp >= NPAD + NB) return;
    bool isC = (warp < NPAD);
    int row = isC ? warp : warp - NPAD;
    if (isC && row >= NC) {   // pad rows
        #pragma unroll
        for (int t = 0; t < 4; t++)
            g_chi[(size_t)row * ND + lane + 32 * t] = __float2bfloat16(0.f);
        if (lane == 0) g_cn[row] = 1e9f;
        return;
    }
    const float* src = isC ? (cents + (size_t)row * ND) : (feats + (size_t)row * ND);
    float x[4];
    #pragma unroll
    for (int t = 0; t < 4; t++) x[t] = src[lane + 32 * t];

    float s = __fmul_rn(x[0], x[0]);
    s = __fadd_rn(s, __fmul_rn(x[1], x[1]));
    s = __fadd_rn(s, __fmul_rn(x[2], x[2]));
    s = __fadd_rn(s, __fmul_rn(x[3], x[3]));
    #pragma unroll
    for (int o = 16; o; o >>= 1)
        s = __fadd_rn(s, __shfl_down_sync(0xffffffffu, s, o));
    if (lane == 0) { if (isC) g_cn[row] = s; else g_fq[row] = s; }

    #pragma unroll
    for (int t = 0; t < 4; t++) {
        __nv_bfloat16 hi = __float2bfloat16(x[t]);
        size_t o = (size_t)row * ND + lane + 32 * t;
        if (isC) g_chi[o] = hi; else g_fhi[o] = hi;
    }
}

// ---------------- K2: bf16 mma.sync GEMM + aggregated prefilter ----------
__global__ void __launch_bounds__(256, 2) k_gemm() {
    extern __shared__ char smem[];
    uint32_t sb = sm2u(smem);
    int tid = threadIdx.x;
    int wid = tid >> 5, lid = tid & 31;
    int m0 = blockIdx.x * 128;
    int n0 = blockIdx.y * 128;

    if (tid < 128) {
        *(float*)(smem + OFF_CN + tid * 4) = g_cn[n0 + tid];
        *(int*)(smem + OFF_SC + tid * 4) = 0;
    }

    // fill 2 tiles: row-major 128 x 128 bf16, padded stride 136 elems
    for (int t = tid; t < 2048; t += 256) {
        int r = t >> 4, k8 = (t & 15) * 8;
        uint32_t so = (uint32_t)(r * TSTR + k8) * 2;
        *(uint4*)(smem + TA + so) = *(const uint4*)(g_fhi + (size_t)(m0 + r) * ND + k8);
        *(uint4*)(smem + TB + so) = *(const uint4*)(g_chi + (size_t)(n0 + r) * ND + k8);
    }
    __syncthreads();

    int wm = wid & 1, wn = wid >> 1;
    int lrow = lid & 15;
    int cg   = lid >> 4;

    float c[4][4][4];
    #pragma unroll
    for (int i = 0; i < 4; i++)
        #pragma unroll
        for (int j = 0; j < 4; j++)
            #pragma unroll
            for (int v = 0; v < 4; v++) c[i][j][v] = 0.f;

    #pragma unroll
    for (int kk = 0; kk < 128; kk += 16) {
        uint32_t af[4][4], bf[2][4];
        #pragma unroll
        for (int ms = 0; ms < 4; ms++) {
            uint32_t ad = sb + TA + (uint32_t)((wm * 64 + ms * 16 + lrow) * TSTR + kk + cg * 8) * 2;
            ldsm4(af[ms][0], af[ms][1], af[ms][2], af[ms][3], ad);
        }
        #pragma unroll
        for (int g = 0; g < 2; g++) {
            uint32_t bd = sb + TB + (uint32_t)((wn * 32 + g * 16 + lrow) * TSTR + kk + cg * 8) * 2;
            ldsm4(bf[g][0], bf[g][1], bf[g][2], bf[g][3], bd);
        }
        #pragma unroll
        for (int ms = 0; ms < 4; ms++)
            #pragma unroll
            for (int ns = 0; ns < 4; ns++) {
                uint32_t b2[2] = { bf[ns >> 1][ns & 1], bf[ns >> 1][(ns & 1) + 2] };
                mma16816(c[ms][ns], af[ms], b2);
            }
    }

    // ---- epilogue: CTA-aggregated candidate append ----
    const float* cns = (const float*)(smem + OFF_CN);
    int* scnt = (int*)(smem + OFF_SC);
    int* sgb  = (int*)(smem + OFF_GB);
    uint32_t masks[8];
    int lbase[8];

    #pragma unroll
    for (int p = 0; p < 8; p++) {
        int ms = p >> 1, half = p & 1;
        int qloc = wm * 64 + ms * 16 + half * 8 + (lid >> 2);
        uint32_t mk = 0; int cnt = 0;
        #pragma unroll
        for (int ns = 0; ns < 4; ns++)
            #pragma unroll
            for (int e = 0; e < 2; e++) {
                int nn = wn * 32 + 2 * (lid & 3) + ns * 8 + e;
                float rel = cns[nn] - 2.0f * c[ms][ns][half * 2 + e];
                if (rel < HRANGE) { mk |= 1u << (ns * 2 + e); cnt++; }
            }
        masks[p] = mk;
        lbase[p] = cnt ? atomicAdd(&scnt[qloc], cnt) : 0;
    }
    __syncthreads();
    if (tid < 128) {
        int c128 = scnt[tid];
        sgb[tid] = c128 ? atomicAdd(&g_cnt[m0 + tid], c128) : 0;
    }
    __syncthreads();

    #pragma unroll
    for (int p = 0; p < 8; p++) {
        uint32_t mk = masks[p];
        if (!mk) continue;
        int ms = p >> 1, half = p & 1;
        int qloc = wm * 64 + ms * 16 + half * 8 + (lid >> 2);
        int q = m0 + qloc;
        int base = sgb[qloc] + lbase[p];
        int r = 0;
        #pragma unroll
        for (int ns = 0; ns < 4; ns++)
            #pragma unroll
            for (int e = 0; e < 2; e++) {
                if (mk & (1u << (ns * 2 + e))) {
                    int nn = wn * 32 + 2 * (lid & 3) + ns * 8 + e;
                    float rel = cns[nn] - 2.0f * c[ms][ns][half * 2 + e];
                    int pos = base + r; r++;
                    if (pos < CAPQ)
                        g_cand[(size_t)q * CAPQ + pos] = make_float2(rel, __int_as_float(n0 + nn));
                }
            }
    }
}

// ---------------- K3: select finalists (staged coalesced recompute) -------
__global__ void __launch_bounds__(256, 6) k_sel(const float* __restrict__ feats,
                                                const float* __restrict__ cents) {
    __shared__ float vstage[BROWS][129];  // 33 KB; stride 129 words: conflict-free
    __shared__ int   sidx[FCAP];          // accepted centre indices
    __shared__ int   hist[HB];
    __shared__ float thr_s;
    __shared__ int   fcnt;
    __shared__ float ff[ND];

    int q = blockIdx.x, tid = threadIdx.x;
    int M = g_cnt[q]; if (M > CAPQ) M = CAPQ;
    const float2* cand = g_cand + (size_t)q * CAPQ;
    const float4* cand4 = (const float4*)cand;
    int Mp = (M + 1) >> 1;

    for (int i = tid; i < HB; i += 256) hist[i] = 0;
    if (tid == 0) fcnt = 0;
    if (tid < ND) ff[tid] = feats[(size_t)q * ND + tid];
    __syncthreads();

    // Phase A: hist streaming pass (float4 = 2 candidates per load)
    #pragma unroll 2
    for (int i = tid; i < Mp; i += 256) {
        float4 v = cand4[i];
        {
            int b = (int)(v.x * 2.0f);
            if (b < 0) b = 0;
            if (b > HB - 1) b = HB - 1;
            atomicAdd(&hist[b], 1);
        }
        if (2 * i + 1 < M) {
            int b = (int)(v.z * 2.0f);
            if (b < 0) b = 0;
            if (b > HB - 1) b = HB - 1;
            atomicAdd(&hist[b], 1);
        }
    }
    __syncthreads();
    if (tid == 0) {
        int cum = 0; float t = HRANGE;
        for (int b = 0; b < HB; b++) {
            cum += hist[b];
            if (cum >= KNN) { t = (float)(b + 1) * HBW; break; }
        }
        thr_s = t;
    }
    __syncthreads();
    float t = thr_s + TMARG;

    // Phase B: rescan (L2-hot) -> accepted index list in smem
    for (int i = tid; i < M; i += 256) {
        float2 v = cand[i];
        if (v.x < t) {
            int p = atomicAdd(&fcnt, 1);
            if (p < FCAP) sidx[p] = __float_as_int(v.y);
        }
    }
    __syncthreads();
    int Fc = fcnt; if (Fc > FCAP) Fc = FCAP;
    float fq = g_fq[q];
    float2* fin = g_fin + (size_t)q * FCAP;

    // Phase C: batches of 64 rows — coalesced copy into smem, then each of
    // 64 threads runs the bit-exact ascending-k FFMA chain from smem.
    for (int b0 = 0; b0 < Fc; b0 += BROWS) {
        int nrows = Fc - b0; if (nrows > BROWS) nrows = BROWS;
        __syncthreads();   // protect vstage reuse
        // copy: flat index f = r*128 + k; consecutive tid -> consecutive k
        for (int f = tid; f < nrows * ND; f += 256) {
            int r = f >> 7, k = f & 127;
            vstage[r][k] = cents[(size_t)sidx[b0 + r] * ND + k];
        }
        __syncthreads();
        if (tid < nrows) {
            int ix = sidx[b0 + tid];
            const float* vr = vstage[tid];
            float acc = 0.f;
            #pragma unroll 16
            for (int k = 0; k < ND; k++)
                acc = fmaf(ff[k], vr[k], acc);
            float d2 = __fadd_rn(__fadd_rn(fq, g_cn[ix]), __fmul_rn(-2.0f, acc));
            fin[b0 + tid] = make_float2(d2, __int_as_float(ix));
        }
    }
    if (tid == 0) g_fcnt[q] = Fc;
}

// ---------------- K4: sort + weight + scatter + normalize + output --------
__global__ void __launch_bounds__(256) k_out(const float* __restrict__ wt,
                                             const void* __restrict__ lab,
                                             float* __restrict__ out,
                                             int out_size) {
    __shared__ float sd[FCAP];
    __shared__ int   si[FCAP];
    __shared__ int   skey[256];
    __shared__ float swv[256];
    __shared__ float pcl[NCL];
    __shared__ float red[256];

    int q = blockIdx.x, tid = threadIdx.x;
    int Fc = g_fcnt[q];
    int P = 256; while (P < Fc) P <<= 1;   // <= FCAP = 512
    const float2* fin = g_fin + (size_t)q * FCAP;

    for (int i = tid; i < P; i += 256) {
        if (i < Fc) { float2 v = fin[i]; sd[i] = v.x; si[i] = __float_as_int(v.y); }
        else        { sd[i] = 1e30f;     si[i] = 0x7fffffff; }
    }
    __syncthreads();

    // bitonic ascending sort on (d2, idx), lower index on ties — canonical
    for (int len = 2; len <= P; len <<= 1) {
        for (int s = len >> 1; s > 0; s >>= 1) {
            for (int i = tid; i < P; i += 256) {
                int j = i ^ s;
                if (j > i) {
                    bool up = ((i & len) == 0);
                    float di = sd[i], dj = sd[j];
                    int   ii = si[i], ij = si[j];
                    bool  gt = (di > dj) || (di == dj && ii > ij);
                    if (gt == up) { sd[i] = dj; sd[j] = di; si[i] = ij; si[j] = ii; }
                }
            }
            __syncthreads();
        }
    }

    int Ke = (Fc < KNN) ? Fc : KNN;
    int is64 = g_lab64;
    {
        int j = tid;
        if (j < Ke) {
            float d2 = sd[j]; if (d2 < 0.f) d2 = 0.f;
            int ix = si[j];
            int lb = is64 ? (int)((const long long*)lab)[ix] : ((const int*)lab)[ix];
            skey[j] = lb * 256 + j;
            swv[j]  = expf(__fmul_rn(-d2, GCONST)) * expf(wt[ix]);
        } else {
            skey[j] = 0x7fffffff;
            swv[j]  = 0.f;
        }
    }
    __syncthreads();

    // bitonic sort 256 by (label, rank) key — one element per thread
    for (int len = 2; len <= 256; len <<= 1) {
        for (int s = len >> 1; s > 0; s >>= 1) {
            int i = tid, j = i ^ s;
            if (j > i) {
                bool up = ((i & len) == 0);
                int   ki = skey[i], kj = skey[j];
                float wi = swv[i],  wj = swv[j];
                if ((ki > kj) == up) { skey[i] = kj; skey[j] = ki; swv[i] = wj; swv[j] = wi; }
            }
            __syncthreads();
        }
    }

    for (int c = tid; c < NCL; c += 256) pcl[c] = 0.f;
    __syncthreads();

    // segment-head sums (within-label order = ascending rank — matches ref)
    {
        int j = tid;
        int key = skey[j];
        if (key != 0x7fffffff) {
            int lb = key >> 8;
            bool head = (j == 0) || ((skey[j - 1] >> 8) != lb);
            if (head) {
                float s = 0.f;
                for (int k2 = j; k2 < 256; k2++) {
                    int k = skey[k2];
                    if (k == 0x7fffffff || (k >> 8) != lb) break;
                    s += swv[k2];
                }
                pcl[lb] = s;
            }
        }
    }
    __syncthreads();

    float partial = 0.f;
    for (int c = tid; c < NCL; c += 256) {
        float p = pcl[c];
        if (p == 0.f) { p = 1e-10f; pcl[c] = p; }
        partial += p;
    }
    red[tid] = partial;
    __syncthreads();
    #pragma unroll
    for (int o = 128; o; o >>= 1) {
        if (tid < o) red[tid] += red[tid + o];
        __syncthreads();
    }
    float S = red[0];

    for (int c = tid; c < NCL; c += 256) {
        float pn = pcl[c] / S;
        size_t o1 = (size_t)q * NCL + c;
        size_t o2 = (size_t)NB * NCL + o1;
        if (o1 < (size_t)out_size) out[o1] = logf(pn);
        if (o2 < (size_t)out_size) out[o2] = pn;
    }
}

// ---------------- launch ----------------
extern "C" void kernel_launch(void* const* d_in, const int* in_sizes, int n_in,
                              void* d_out, int out_size) {
    const float* feats = (const float*)d_in[0];
    const float* cents = (const float*)d_in[1];
    const float* wt    = (const float*)d_in[2];
    const void*  lab   = d_in[3];

    cudaFuncSetAttribute(k_gemm, cudaFuncAttributeMaxDynamicSharedMemorySize, SMEM_SZ);

    k_zero<<<(NB + 255) / 256, 256>>>((const int*)lab);
    k_prep<<<((NPAD + NB) * 32 + 255) / 256, 256>>>(feats, cents);
    k_gemm<<<dim3(NB / 128, NPAD / 128), 256, SMEM_SZ>>>();
    k_sel<<<NB, 256>>>(feats, cents);
    k_out<<<NB, 256>>>(wt, lab, (float*)d_out, out_size);
}

// round 17
// speedup vs baseline: 1.1384x; 1.0119x over previous
#include <cuda_runtime.h>
#include <cuda_bf16.h>
#include <math.h>
#include <stdint.h>

// Problem constants
#define NB    2048
#define NC    100000
#define NPAD  100096      // 782 * 128
#define ND    128
#define KNN   200
#define NCL   1000
#define GCONST 0.005f

#define HB    144
#define HBW   0.5f
#define HRANGE 72.0f      // rank-200 rel <= ~60 for all queries (>10 sigma margin)
#define CAPQ  8192        // prefilter capacity/query (mean ~2250, max ~3800)
#define FCAP  512         // finalist capacity/query (expected ~235)
#define TMARG 1.0f        // margin >> bf16 dot noise (4 sigma ~ 0.22) + bin width
#define BROWS 64          // staged recompute batch rows

#define NT_TOT 782        // n-tiles (NPAD/128)
#define NSPLIT 18         // persistent CTA columns: 16*18=288 CTAs = 1 wave

// -------- device scratch --------
static __device__ __align__(16) __nv_bfloat16 g_chi[(size_t)NPAD * ND];
static __device__ __align__(16) __nv_bfloat16 g_fhi[(size_t)NB * ND];
static __device__ float  g_cn[NPAD];
static __device__ float  g_fq[NB];
static __device__ int    g_cnt[NB];
static __device__ __align__(16) float2 g_cand[(size_t)NB * CAPQ];  // (rel, idx)
static __device__ float2 g_fin[(size_t)NB * FCAP];                 // (d2, idx)
static __device__ int    g_fcnt[NB];
static __device__ int    g_lab64;

// -------- baseline-PTX helpers --------
__device__ __forceinline__ uint32_t sm2u(const void* p) {
    uint32_t a;
    asm("{ .reg .u64 t; cvta.to.shared.u64 t, %1; cvt.u32.u64 %0, t; }" : "=r"(a) : "l"(p));
    return a;
}
__device__ __forceinline__ void ldsm4(uint32_t& r0, uint32_t& r1, uint32_t& r2, uint32_t& r3,
                                      uint32_t addr) {
    asm volatile("ldmatrix.sync.aligned.m8n8.x4.shared.b16 {%0,%1,%2,%3}, [%4];"
                 : "=r"(r0), "=r"(r1), "=r"(r2), "=r"(r3) : "r"(addr));
}
__device__ __forceinline__ void mma16816(float* c, const uint32_t* a, const uint32_t* b) {
    asm volatile(
        "mma.sync.aligned.m16n8k16.row.col.f32.bf16.bf16.f32 "
        "{%0,%1,%2,%3},{%4,%5,%6,%7},{%8,%9},{%0,%1,%2,%3};"
        : "+f"(c[0]), "+f"(c[1]), "+f"(c[2]), "+f"(c[3])
        : "r"(a[0]), "r"(a[1]), "r"(a[2]), "r"(a[3]), "r"(b[0]), "r"(b[1]));
}
__device__ __forceinline__ void cpa16(uint32_t saddr, const void* g) {
    asm volatile("cp.async.cg.shared.global [%0], [%1], 16;" :: "r"(saddr), "l"(g));
}
#define CP_COMMIT() asm volatile("cp.async.commit_group;" ::: "memory")
#define CP_WAIT1()  asm volatile("cp.async.wait_group 1;" ::: "memory")

// SMEM layout (dynamic): A + double-buffered B + double cn + counters
#define TSTR   136
#define TBYTES (128 * TSTR * 2)        // 34816
#define TA     0
#define TBB(b) (TBYTES + (b) * TBYTES) // 34816 / 69632
#define CNB(b) (3 * TBYTES + (b) * 512)// 104448 / 104960
#define OFF_SC (3 * TBYTES + 1024)     // 105472
#define OFF_GB (OFF_SC + 512)          // 105984
#define SMEM_SZ (OFF_GB + 512)         // 106496 (~104 KB) -> 2 CTAs/SM

// ---------------- K0: zero counters + label dtype sniff ----------------
__global__ void k_zero(const int* __restrict__ labw) {
    int i = blockIdx.x * blockDim.x + threadIdx.x;
    if (i < NB) g_cnt[i] = 0;
    if (i == 0) {
        int any = 0;
        #pragma unroll
        for (int j = 1; j < 64; j += 2) any |= labw[j];
        g_lab64 = (any == 0) ? 1 : 0;
    }
}

// ---------------- K1: norms (bit-exact XLA pattern) + bf16 cast ----------
__global__ void k_prep(const float* __restrict__ feats, const float* __restrict__ cents) {
    int warp = (blockIdx.x * blockDim.x + threadIdx.x) >> 5;
    int lane = threadIdx.x & 31;
    if (warp >= NPAD + NB) return;
    bool isC = (warp < NPAD);
    int row = isC ? warp : warp - NPAD;
    if (isC && row >= NC) {   // pad rows
        #pragma unroll
        for (int t = 0; t < 4; t++)
            g_chi[(size_t)row * ND + lane + 32 * t] = __float2bfloat16(0.f);
        if (lane == 0) g_cn[row] = 1e9f;
        return;
    }
    const float* src = isC ? (cents + (size_t)row * ND) : (feats + (size_t)row * ND);
    float x[4];
    #pragma unroll
    for (int t = 0; t < 4; t++) x[t] = src[lane + 32 * t];

    float s = __fmul_rn(x[0], x[0]);
    s = __fadd_rn(s, __fmul_rn(x[1], x[1]));
    s = __fadd_rn(s, __fmul_rn(x[2], x[2]));
    s = __fadd_rn(s, __fmul_rn(x[3], x[3]));
    #pragma unroll
    for (int o = 16; o; o >>= 1)
        s = __fadd_rn(s, __shfl_down_sync(0xffffffffu, s, o));
    if (lane == 0) { if (isC) g_cn[row] = s; else g_fq[row] = s; }

    #pragma unroll
    for (int t = 0; t < 4; t++) {
        __nv_bfloat16 hi = __float2bfloat16(x[t]);
        size_t o = (size_t)row * ND + lane + 32 * t;
        if (isC) g_chi[o] = hi; else g_fhi[o] = hi;
    }
}

// stage one B tile (+ its cn slice) into buffer b via cp.async
__device__ __forceinline__ void stageB(uint32_t sb, int b, int nt, int tid) {
    const __nv_bfloat16* src = g_chi + (size_t)nt * 128 * ND;
    uint32_t dst = sb + TBB(b);
    for (int t = tid; t < 2048; t += 256) {
        int r = t >> 4, k8 = (t & 15) * 8;
        cpa16(dst + (uint32_t)(r * TSTR + k8) * 2, src + (size_t)r * ND + k8);
    }
    if (tid < 32) cpa16(sb + CNB(b) + tid * 16, g_cn + nt * 128 + tid * 4);
}

// ---------------- K2: persistent bf16 GEMM, cp.async double-buffered B ----
__global__ void __launch_bounds__(256, 2) k_gemm() {
    extern __shared__ char smem[];
    uint32_t sb = sm2u(smem);
    int tid = threadIdx.x;
    int wid = tid >> 5, lid = tid & 31;
    int m0 = blockIdx.x * 128;

    // stage A tile (once) + first B into group 0
    for (int t = tid; t < 2048; t += 256) {
        int r = t >> 4, k8 = (t & 15) * 8;
        cpa16(sb + TA + (uint32_t)(r * TSTR + k8) * 2,
              g_fhi + (size_t)(m0 + r) * ND + k8);
    }
    int nt = blockIdx.y;
    stageB(sb, 0, nt, tid);
    CP_COMMIT();

    int wm = wid & 1, wn = wid >> 1;
    int lrow = lid & 15;
    int cg   = lid >> 4;
    int* scnt = (int*)(smem + OFF_SC);
    int* sgb  = (int*)(smem + OFF_GB);
    int buf = 0;

    while (nt < NT_TOT) {
        int ntn = nt + NSPLIT;
        if (ntn < NT_TOT) stageB(sb, buf ^ 1, ntn, tid);
        CP_COMMIT();
        CP_WAIT1();            // current buf (and A) resident
        __syncthreads();

        // ---- compute 128x128 tile from TA, TB(buf) ----
        float c[4][4][4];
        #pragma unroll
        for (int i = 0; i < 4; i++)
            #pragma unroll
            for (int j = 0; j < 4; j++)
                #pragma unroll
                for (int v = 0; v < 4; v++) c[i][j][v] = 0.f;

        uint32_t Bb = sb + TBB(buf);
        #pragma unroll
        for (int kk = 0; kk < 128; kk += 16) {
            uint32_t af[4][4], bfr[2][4];
            #pragma unroll
            for (int ms = 0; ms < 4; ms++) {
                uint32_t ad = sb + TA + (uint32_t)((wm * 64 + ms * 16 + lrow) * TSTR + kk + cg * 8) * 2;
                ldsm4(af[ms][0], af[ms][1], af[ms][2], af[ms][3], ad);
            }
            #pragma unroll
            for (int g = 0; g < 2; g++) {
                uint32_t bd = Bb + (uint32_t)((wn * 32 + g * 16 + lrow) * TSTR + kk + cg * 8) * 2;
                ldsm4(bfr[g][0], bfr[g][1], bfr[g][2], bfr[g][3], bd);
            }
            #pragma unroll
            for (int ms = 0; ms < 4; ms++)
                #pragma unroll
                for (int ns = 0; ns < 4; ns++) {
                    uint32_t b2[2] = { bfr[ns >> 1][ns & 1], bfr[ns >> 1][(ns & 1) + 2] };
                    mma16816(c[ms][ns], af[ms], b2);
                }
        }

        // ---- epilogue: CTA-aggregated candidate append ----
        int n0 = nt * 128;
        const float* cns = (const float*)(smem + CNB(buf));
        if (tid < 128) scnt[tid] = 0;
        __syncthreads();

        uint32_t masks[8];
        int lbase[8];
        #pragma unroll
        for (int p = 0; p < 8; p++) {
            int ms = p >> 1, half = p & 1;
            int qloc = wm * 64 + ms * 16 + half * 8 + (lid >> 2);
            uint32_t mk = 0; int cnt = 0;
            #pragma unroll
            for (int ns = 0; ns < 4; ns++)
                #pragma unroll
                for (int e = 0; e < 2; e++) {
                    int nn = wn * 32 + 2 * (lid & 3) + ns * 8 + e;
                    float rel = cns[nn] - 2.0f * c[ms][ns][half * 2 + e];
                    if (rel < HRANGE) { mk |= 1u << (ns * 2 + e); cnt++; }
                }
            masks[p] = mk;
            lbase[p] = cnt ? atomicAdd(&scnt[qloc], cnt) : 0;
        }
        __syncthreads();
        if (tid < 128) {
            int c128 = scnt[tid];
            sgb[tid] = c128 ? atomicAdd(&g_cnt[m0 + tid], c128) : 0;
        }
        __syncthreads();

        #pragma unroll
        for (int p = 0; p < 8; p++) {
            uint32_t mk = masks[p];
            if (!mk) continue;
            int ms = p >> 1, half = p & 1;
            int qloc = wm * 64 + ms * 16 + half * 8 + (lid >> 2);
            int q = m0 + qloc;
            int base = sgb[qloc] + lbase[p];
            int r = 0;
            #pragma unroll
            for (int ns = 0; ns < 4; ns++)
                #pragma unroll
                for (int e = 0; e < 2; e++) {
                    if (mk & (1u << (ns * 2 + e))) {
                        int nn = wn * 32 + 2 * (lid & 3) + ns * 8 + e;
                        float rel = cns[nn] - 2.0f * c[ms][ns][half * 2 + e];
                        int pos = base + r; r++;
                        if (pos < CAPQ)
                            g_cand[(size_t)q * CAPQ + pos] = make_float2(rel, __int_as_float(n0 + nn));
                    }
                }
        }
        __syncthreads();   // protect TB(buf)/CN(buf) reuse next iteration
        nt = ntn; buf ^= 1;
    }
}

// ---------------- K3: select finalists (staged coalesced recompute) -------
__global__ void __launch_bounds__(256, 6) k_sel(const float* __restrict__ feats,
                                                const float* __restrict__ cents) {
    __shared__ float vstage[BROWS][129];  // 33 KB; stride 129 words: conflict-free
    __shared__ int   sidx[FCAP];          // accepted centre indices
    __shared__ int   hist[HB];
    __shared__ float thr_s;
    __shared__ int   fcnt;
    __shared__ float ff[ND];

    int q = blockIdx.x, tid = threadIdx.x;
    int M = g_cnt[q]; if (M > CAPQ) M = CAPQ;
    const float2* cand = g_cand + (size_t)q * CAPQ;
    const float4* cand4 = (const float4*)cand;
    int Mp = (M + 1) >> 1;

    for (int i = tid; i < HB; i += 256) hist[i] = 0;
    if (tid == 0) fcnt = 0;
    if (tid < ND) ff[tid] = feats[(size_t)q * ND + tid];
    __syncthreads();

    // Phase A: hist streaming pass (float4 = 2 candidates per load)
    #pragma unroll 2
    for (int i = tid; i < Mp; i += 256) {
        float4 v = cand4[i];
        {
            int b = (int)(v.x * 2.0f);
            if (b < 0) b = 0;
            if (b > HB - 1) b = HB - 1;
            atomicAdd(&hist[b], 1);
        }
        if (2 * i + 1 < M) {
            int b = (int)(v.z * 2.0f);
            if (b < 0) b = 0;
            if (b > HB - 1) b = HB - 1;
            atomicAdd(&hist[b], 1);
        }
    }
    __syncthreads();
    if (tid == 0) {
        int cum = 0; float t = HRANGE;
        for (int b = 0; b < HB; b++) {
            cum += hist[b];
            if (cum >= KNN) { t = (float)(b + 1) * HBW; break; }
        }
        thr_s = t;
    }
    __syncthreads();
    float t = thr_s + TMARG;

    // Phase B: rescan (L2-hot) -> accepted index list in smem
    for (int i = tid; i < M; i += 256) {
        float2 v = cand[i];
        if (v.x < t) {
            int p = atomicAdd(&fcnt, 1);
            if (p < FCAP) sidx[p] = __float_as_int(v.y);
        }
    }
    __syncthreads();
    int Fc = fcnt; if (Fc > FCAP) Fc = FCAP;
    float fq = g_fq[q];
    float2* fin = g_fin + (size_t)q * FCAP;

    // Phase C: batches of 64 rows — coalesced copy into smem, then each of
    // 64 threads runs the bit-exact ascending-k FFMA chain from smem.
    for (int b0 = 0; b0 < Fc; b0 += BROWS) {
        int nrows = Fc - b0; if (nrows > BROWS) nrows = BROWS;
        __syncthreads();   // protect vstage reuse
        for (int f = tid; f < nrows * ND; f += 256) {
            int r = f >> 7, k = f & 127;
            vstage[r][k] = cents[(size_t)sidx[b0 + r] * ND + k];
        }
        __syncthreads();
        if (tid < nrows) {
            int ix = sidx[b0 + tid];
            const float* vr = vstage[tid];
            float acc = 0.f;
            #pragma unroll 16
            for (int k = 0; k < ND; k++)
                acc = fmaf(ff[k], vr[k], acc);
            float d2 = __fadd_rn(__fadd_rn(fq, g_cn[ix]), __fmul_rn(-2.0f, acc));
            fin[b0 + tid] = make_float2(d2, __int_as_float(ix));
        }
    }
    if (tid == 0) g_fcnt[q] = Fc;
}

// ---------------- K4: sort + weight + scatter + normalize + output --------
__global__ void __launch_bounds__(256) k_out(const float* __restrict__ wt,
                                             const void* __restrict__ lab,
                                             float* __restrict__ out,
                                             int out_size) {
    __shared__ float sd[FCAP];
    __shared__ int   si[FCAP];
    __shared__ int   skey[256];
    __shared__ float swv[256];
    __shared__ float pcl[NCL];
    __shared__ float red[256];

    int q = blockIdx.x, tid = threadIdx.x;
    int Fc = g_fcnt[q];
    int P = 256; while (P < Fc) P <<= 1;   // <= FCAP = 512
    const float2* fin = g_fin + (size_t)q * FCAP;

    for (int i = tid; i < P; i += 256) {
        if (i < Fc) { float2 v = fin[i]; sd[i] = v.x; si[i] = __float_as_int(v.y); }
        else        { sd[i] = 1e30f;     si[i] = 0x7fffffff; }
    }
    __syncthreads();

    // bitonic ascending sort on (d2, idx), lower index on ties — canonical
    for (int len = 2; len <= P; len <<= 1) {
        for (int s = len >> 1; s > 0; s >>= 1) {
            for (int i = tid; i < P; i += 256) {
                int j = i ^ s;
                if (j > i) {
                    bool up = ((i & len) == 0);
                    float di = sd[i], dj = sd[j];
                    int   ii = si[i], ij = si[j];
                    bool  gt = (di > dj) || (di == dj && ii > ij);
                    if (gt == up) { sd[i] = dj; sd[j] = di; si[i] = ij; si[j] = ii; }
                }
            }
            __syncthreads();
        }
    }

    int Ke = (Fc < KNN) ? Fc : KNN;
    int is64 = g_lab64;
    {
        int j = tid;
        if (j < Ke) {
            float d2 = sd[j]; if (d2 < 0.f) d2 = 0.f;
            int ix = si[j];
            int lb = is64 ? (int)((const long long*)lab)[ix] : ((const int*)lab)[ix];
            skey[j] = lb * 256 + j;
            swv[j]  = expf(__fmul_rn(-d2, GCONST)) * expf(wt[ix]);
        } else {
            skey[j] = 0x7fffffff;
            swv[j]  = 0.f;
        }
    }
    __syncthreads();

    // bitonic sort 256 by (label, rank) key — one element per thread
    for (int len = 2; len <= 256; len <<= 1) {
        for (int s = len >> 1; s > 0; s >>= 1) {
            int i = tid, j = i ^ s;
            if (j > i) {
                bool up = ((i & len) == 0);
                int   ki = skey[i], kj = skey[j];
                float wi = swv[i],  wj = swv[j];
                if ((ki > kj) == up) { skey[i] = kj; skey[j] = ki; swv[i] = wj; swv[j] = wi; }
            }
            __syncthreads();
        }
    }

    for (int c = tid; c < NCL; c += 256) pcl[c] = 0.f;
    __syncthreads();

    // segment-head sums (within-label order = ascending rank — matches ref)
    {
        int j = tid;
        int key = skey[j];
        if (key != 0x7fffffff) {
            int lb = key >> 8;
            bool head = (j == 0) || ((skey[j - 1] >> 8) != lb);
            if (head) {
                float s = 0.f;
                for (int k2 = j; k2 < 256; k2++) {
                    int k = skey[k2];
                    if (k == 0x7fffffff || (k >> 8) != lb) break;
                    s += swv[k2];
                }
                pcl[lb] = s;
            }
        }
    }
    __syncthreads();

    float partial = 0.f;
    for (int c = tid; c < NCL; c += 256) {
        float p = pcl[c];
        if (p == 0.f) { p = 1e-10f; pcl[c] = p; }
        partial += p;
    }
    red[tid] = partial;
    __syncthreads();
    #pragma unroll
    for (int o = 128; o; o >>= 1) {
        if (tid < o) red[tid] += red[tid + o];
        __syncthreads();
    }
    float S = red[0];

    for (int c = tid; c < NCL; c += 256) {
        float pn = pcl[c] / S;
        size_t o1 = (size_t)q * NCL + c;
        size_t o2 = (size_t)NB * NCL + o1;
        if (o1 < (size_t)out_size) out[o1] = logf(pn);
        if (o2 < (size_t)out_size) out[o2] = pn;
    }
}

// ---------------- launch ----------------
extern "C" void kernel_launch(void* const* d_in, const int* in_sizes, int n_in,
                              void* d_out, int out_size) {
    const float* feats = (const float*)d_in[0];
    const float* cents = (const float*)d_in[1];
    const float* wt    = (const float*)d_in[2];
    const void*  lab   = d_in[3];

    cudaFuncSetAttribute(k_gemm, cudaFuncAttributeMaxDynamicSharedMemorySize, SMEM_SZ);

    k_zero<<<(NB + 255) / 256, 256>>>((const int*)lab);
    k_prep<<<((NPAD + NB) * 32 + 255) / 256, 256>>>(feats, cents);
    k_gemm<<<dim3(NB / 128, NSPLIT), 256, SMEM_SZ>>>();
    k_sel<<<NB, 256>>>(feats, cents);
    k_out<<<NB, 256>>>(wt, lab, (float*)d_out, out_size);
}